// round 14
// baseline (speedup 1.0000x reference)
#include <cuda_runtime.h>
#include <cuda_fp16.h>

#define N_NODES 50000
#define N_REL   1000
#define D       128
#define NNZ_MAX 800000

#define FUSE_NB  592          // fused kernel: 4 blocks/SM -> co-resident
#define SORT_NB  391          // sort kernel grid (covers nnz at 8 edges/thread)
#define SCAN2    196          // scanning blocks inside k_sort (256 cnt each)
#define Q        64           // edges per gather warp

// Scratch (allocation-free rule: __device__ globals)
__device__ float g_exp_lr[N_REL];
__device__ float g_coef[N_REL];           // exp / S
__device__ float g_S;
__device__ int   g_cnt[N_NODES];
__device__ int   g_bsum[SCAN2];
__device__ int   g_tick1;                 // ticket barrier (fused, 592-wide)
__device__ int   g_tick2;                 // ticket barrier (sort, 391-wide)
__device__ int   g_offs[N_NODES + 1];
__device__ __align__(16) int g_rank[NNZ_MAX];
// 64-bit packed edge: coef_f32_bits<<32 | col<<16 | row
__device__ __align__(16) unsigned long long g_edges[NNZ_MAX];
__device__ __align__(16) __half g_inh[(size_t)N_NODES * D];   // fp16 features

// Monotonic ticket barrier: counter only grows; each use consumes exactly NBLK
// increments, so boundaries stay multiples of NBLK -> graph-replay-safe.
__device__ __forceinline__ void grid_bar(int* tick, int NBLK) {
    __syncthreads();
    __threadfence();
    if (threadIdx.x == 0) {
        const int t = atomicAdd(tick, 1);
        const int target = (t / NBLK + 1) * NBLK;
        while (atomicAdd(tick, 0) < target) {}
    }
    __syncthreads();
}

// ---------------------------------------------------------------------------
// K1 (fused): phase A: zero cnt/S + relation scores (warp/rel; shift=0 safe)
//             -- bar(592) --
//             phase B: hist+rank+denominator, then fp16 staging.
// (unchanged from R13 — proven)
// ---------------------------------------------------------------------------
__global__ void __launch_bounds__(256, 4)
k_fused(const float* __restrict__ inlayer, const float* __restrict__ dual,
        const float* __restrict__ w, const float* __restrict__ b,
        const int* __restrict__ rowp, const int* __restrict__ relp, int nnz) {
    const int tid  = blockIdx.x * blockDim.x + threadIdx.x;
    const int nthr = FUSE_NB * 256;
    const int lane = threadIdx.x & 31;

    if (tid == 0) g_S = 0.f;
    for (int i = tid; i < N_NODES; i += nthr) g_cnt[i] = 0;

    const int r = tid >> 5;
    if (r < N_REL) {
        const float4 a  = reinterpret_cast<const float4*>(dual + (size_t)r * D)[lane];
        const float4 ww = reinterpret_cast<const float4*>(w)[lane];
        float s = a.x * ww.x + a.y * ww.y + a.z * ww.z + a.w * ww.w;
#pragma unroll
        for (int o = 16; o > 0; o >>= 1) s += __shfl_xor_sync(0xffffffffu, s, o);
        if (lane == 0) {
            s += b[0];
            const float lr = (s > 0.f) ? s : 0.01f * s;
            g_exp_lr[r] = expf(lr);
        }
    }

    grid_bar(&g_tick1, FUSE_NB);

    const int nvec = nnz >> 2;
    {
        const int4* row4 = reinterpret_cast<const int4*>(rowp);
        const int4* rel4 = reinterpret_cast<const int4*>(relp);
        int4* rank4 = reinterpret_cast<int4*>(g_rank);

        float s = 0.f;
        for (int i = tid; i < nvec; i += nthr) {
            const int4 r0 = __ldg(row4 + i);
            const int4 q0 = __ldg(rel4 + i);
            int4 rk;
            rk.x = atomicAdd(&g_cnt[r0.x], 1);
            rk.y = atomicAdd(&g_cnt[r0.y], 1);
            rk.z = atomicAdd(&g_cnt[r0.z], 1);
            rk.w = atomicAdd(&g_cnt[r0.w], 1);
            rank4[i] = rk;
            s += g_exp_lr[q0.x] + g_exp_lr[q0.y] + g_exp_lr[q0.z] + g_exp_lr[q0.w];
        }
        const int e0 = (nvec << 2) + tid;
        if (e0 < nnz) {
            g_rank[e0] = atomicAdd(&g_cnt[__ldg(rowp + e0)], 1);
            s += g_exp_lr[__ldg(relp + e0)];
        }
#pragma unroll
        for (int o = 16; o > 0; o >>= 1) s += __shfl_xor_sync(0xffffffffu, s, o);
        __shared__ float smf[8];
        if ((threadIdx.x & 31) == 0) smf[threadIdx.x >> 5] = s;
        __syncthreads();
        if (threadIdx.x < 32) {
            float v = (threadIdx.x < 8) ? smf[threadIdx.x] : 0.f;
#pragma unroll
            for (int o = 4; o > 0; o >>= 1) v += __shfl_xor_sync(0xffffffffu, v, o);
            if (threadIdx.x == 0) atomicAdd(&g_S, v);
        }
    }

    {   // fp16 staging
        const int nv = (N_NODES * D) / 4;
        const float4* in4 = reinterpret_cast<const float4*>(inlayer);
        uint2* out2 = reinterpret_cast<uint2*>(g_inh);
        for (int i = tid; i < nv; i += nthr) {
            const float4 v = __ldg(in4 + i);
            const __half2 h01 = __floats2half2_rn(v.x, v.y);
            const __half2 h23 = __floats2half2_rn(v.z, v.w);
            uint2 p;
            p.x = *reinterpret_cast<const unsigned*>(&h01);
            p.y = *reinterpret_cast<const unsigned*>(&h23);
            out2[i] = p;
        }
    }
}

// ---------------------------------------------------------------------------
// K2 (sort): scan + offsets + zero-flag + reorder in ONE kernel, 391 blocks.
//  phase 1: blocks 0..195 block-scan g_cnt (256 each); block 200 does coef
//           (g_S is final — K1 completed). Others fall through to barrier.
//  -- bar(391) --
//  phase 2: scanning blocks: base from partials, write g_offs, and zero
//           atomic-candidate output rows (warp-ballot cooperative).
//  -- bar(391) --
//  phase 3: ALL blocks: reorder into 64-bit packed edges (coef folded,
//           pos = offs[row] + rank, no atomics), 8 edges/thread.
// ---------------------------------------------------------------------------
__global__ void __launch_bounds__(256)
k_sort(const int* __restrict__ rowp, const int* __restrict__ colp,
       const int* __restrict__ relp, int nnz, float* __restrict__ out) {
    const int t    = threadIdx.x;
    const int bid  = blockIdx.x;
    const int lane = t & 31;
    const int gid  = bid * 256 + t;
    __shared__ int sm[256];

    // ---- phase 1 ----
    int v = 0, incl = 0;
    if (bid < SCAN2) {
        v = (gid < N_NODES) ? g_cnt[gid] : 0;
        sm[t] = v;
        __syncthreads();
#pragma unroll
        for (int o = 1; o < 256; o <<= 1) {
            const int p = (t >= o) ? sm[t - o] : 0;
            __syncthreads();
            sm[t] += p;
            __syncthreads();
        }
        incl = sm[t];
        if (t == 255) g_bsum[bid] = incl;
    } else if (bid == 200) {
        const float invS = 1.0f / g_S;
        for (int rr = t; rr < N_REL; rr += 256) g_coef[rr] = g_exp_lr[rr] * invS;
        if (t == 0) g_offs[N_NODES] = nnz;
    }

    grid_bar(&g_tick2, SORT_NB);

    // ---- phase 2 ----
    if (bid < SCAN2) {
        sm[t] = (t < bid) ? __ldcg(&g_bsum[t]) : 0;
        __syncthreads();
#pragma unroll
        for (int o = 128; o > 0; o >>= 1) {
            if (t < o) sm[t] += sm[t + o];
            __syncthreads();
        }
        const int base = sm[0];
        const int off  = base + incl - v;
        const bool valid = (gid < N_NODES);
        if (valid) g_offs[gid] = off;

        // zero-flag: rows gather hits with atomics (quota-boundary / empty)
        const int en = off + v;
        bool flag = false;
        if (valid)
            flag = (v == 0) || (off % Q == 0) || (en % Q == 0) ||
                   (en == nnz) || ((off / Q) != ((en - 1) / Q));
        // warp-cooperative zeroing of flagged rows
        unsigned m = __ballot_sync(0xffffffffu, flag);
        const int wbase = gid - lane;           // first gid of this warp
        while (m) {
            const int j = __ffs(m) - 1;
            m &= m - 1;
            reinterpret_cast<float4*>(out + (size_t)(wbase + j) * D)[lane] =
                make_float4(0.f, 0.f, 0.f, 0.f);
        }
    }

    grid_bar(&g_tick2, SORT_NB);

    // ---- phase 3: reorder (all 391 blocks; 8 edges/thread covers nnz) ----
    const int nvec = nnz >> 2;
#pragma unroll
    for (int k = 0; k < 2; k++) {
        const int i = gid * 2 + k;
        if (i < nvec) {
            const int4 r  = __ldg(reinterpret_cast<const int4*>(rowp) + i);
            const int4 c  = __ldg(reinterpret_cast<const int4*>(colp) + i);
            const int4 q  = __ldg(reinterpret_cast<const int4*>(relp) + i);
            const int4 rk = __ldg(reinterpret_cast<const int4*>(g_rank) + i);
            const int p0 = __ldcg(&g_offs[r.x]) + rk.x;
            const int p1 = __ldcg(&g_offs[r.y]) + rk.y;
            const int p2 = __ldcg(&g_offs[r.z]) + rk.z;
            const int p3 = __ldcg(&g_offs[r.w]) + rk.w;
            const unsigned cf0 = __float_as_uint(__ldcg(&g_coef[q.x]));
            const unsigned cf1 = __float_as_uint(__ldcg(&g_coef[q.y]));
            const unsigned cf2 = __float_as_uint(__ldcg(&g_coef[q.z]));
            const unsigned cf3 = __float_as_uint(__ldcg(&g_coef[q.w]));
            g_edges[p0] = ((unsigned long long)cf0 << 32) | ((unsigned)c.x << 16) | (unsigned)r.x;
            g_edges[p1] = ((unsigned long long)cf1 << 32) | ((unsigned)c.y << 16) | (unsigned)r.y;
            g_edges[p2] = ((unsigned long long)cf2 << 32) | ((unsigned)c.z << 16) | (unsigned)r.z;
            g_edges[p3] = ((unsigned long long)cf3 << 32) | ((unsigned)c.w << 16) | (unsigned)r.w;
        }
    }
    const int e = (nvec << 2) + gid;
    if (e < nnz) {
        const int row = __ldg(rowp + e);
        const int pos = __ldcg(&g_offs[row]) + g_rank[e];
        const unsigned cf = __float_as_uint(__ldcg(&g_coef[__ldg(relp + e)]));
        g_edges[pos] = ((unsigned long long)cf << 32) |
                       ((unsigned)__ldg(colp + e) << 16) | (unsigned)row;
    }
}

// ---------------------------------------------------------------------------
// K3: balanced gather (unchanged from R13 — proven 26.6us).
// ---------------------------------------------------------------------------
__device__ __forceinline__ void acc_edge_cvt(uint2 hv, float c, float4& a) {
    const float2 f01 = __half22float2(*reinterpret_cast<const __half2*>(&hv.x));
    const float2 f23 = __half22float2(*reinterpret_cast<const __half2*>(&hv.y));
    a.x = fmaf(c, f01.x, a.x);
    a.y = fmaf(c, f01.y, a.y);
    a.z = fmaf(c, f23.x, a.z);
    a.w = fmaf(c, f23.y, a.w);
}

__device__ __forceinline__ void flush_row(float* __restrict__ out, int row,
                                          const float4& a, bool atomic, int lane) {
    float* p = out + (size_t)row * D + lane * 4;
    if (atomic) {
        asm volatile("red.global.add.v4.f32 [%0], {%1, %2, %3, %4};"
                     :: "l"(p), "f"(a.x), "f"(a.y), "f"(a.z), "f"(a.w)
                     : "memory");
    } else {
        *reinterpret_cast<float4*>(p) = a;
    }
}

__global__ void __launch_bounds__(128)
k_gather(float* __restrict__ out, int nnz) {
    const int lane = threadIdx.x & 31;
    const int wid  = (blockIdx.x * blockDim.x + threadIdx.x) >> 5;
    const int base = wid * Q;
    if (base >= nnz) return;
    const int end = min(base + Q, nnz);

    int   currow = (int)((unsigned)__ldg(&g_edges[base]) & 0xFFFFu);
    bool  first  = true;
    float4 acc   = make_float4(0.f, 0.f, 0.f, 0.f);

    int i = base;
    for (; i + 3 < end; i += 4) {
        const ulonglong2 ea = __ldg(reinterpret_cast<const ulonglong2*>(g_edges + i));
        const ulonglong2 eb = __ldg(reinterpret_cast<const ulonglong2*>(g_edges + i + 2));
        const uint2 v0 = __ldg(reinterpret_cast<const uint2*>(
                g_inh + (size_t)((unsigned)(ea.x >> 16) & 0xFFFFu) * D) + lane);
        const uint2 v1 = __ldg(reinterpret_cast<const uint2*>(
                g_inh + (size_t)((unsigned)(ea.y >> 16) & 0xFFFFu) * D) + lane);
        const uint2 v2 = __ldg(reinterpret_cast<const uint2*>(
                g_inh + (size_t)((unsigned)(eb.x >> 16) & 0xFFFFu) * D) + lane);
        const uint2 v3 = __ldg(reinterpret_cast<const uint2*>(
                g_inh + (size_t)((unsigned)(eb.y >> 16) & 0xFFFFu) * D) + lane);

        const unsigned long long eds[4] = {ea.x, ea.y, eb.x, eb.y};
        const uint2 vs[4] = {v0, v1, v2, v3};
#pragma unroll
        for (int k = 0; k < 4; k++) {
            const int row = (int)((unsigned)eds[k] & 0xFFFFu);
            if (row != currow) {
                flush_row(out, currow, acc, first, lane);
                first = false;
                acc = make_float4(0.f, 0.f, 0.f, 0.f);
                currow = row;
            }
            const float c = __uint_as_float((unsigned)(eds[k] >> 32));
            acc_edge_cvt(vs[k], c, acc);
        }
    }
    for (; i < end; i++) {
        const unsigned long long ed = __ldg(&g_edges[i]);
        const int row = (int)((unsigned)ed & 0xFFFFu);
        if (row != currow) {
            flush_row(out, currow, acc, first, lane);
            first = false;
            acc = make_float4(0.f, 0.f, 0.f, 0.f);
            currow = row;
        }
        const uint2 v = __ldg(reinterpret_cast<const uint2*>(
                g_inh + (size_t)((unsigned)(ed >> 16) & 0xFFFFu) * D) + lane);
        const float c = __uint_as_float((unsigned)(ed >> 32));
        acc_edge_cvt(v, c, acc);
    }
    flush_row(out, currow, acc, true, lane);
}

// ---------------------------------------------------------------------------
// kernel_launch
// Inputs: 0 inlayer [N,D] f32 | 1 dual [R,D] f32 | 2 conv_w [D] f32
//         3 conv_b [1] f32    | 4 edge_idx [2,NNZ] i32 | 5 edge_rel [NNZ] i32
// Output: [N, D] f32
// ---------------------------------------------------------------------------
extern "C" void kernel_launch(void* const* d_in, const int* in_sizes, int n_in,
                              void* d_out, int out_size) {
    const float* inlayer = (const float*)d_in[0];
    const float* dual    = (const float*)d_in[1];
    const float* conv_w  = (const float*)d_in[2];
    const float* conv_b  = (const float*)d_in[3];
    const int*   eidx    = (const int*)d_in[4];
    const int*   erel    = (const int*)d_in[5];
    float*       out     = (float*)d_out;

    const int nnz = in_sizes[5];
    const int* rowp = eidx;
    const int* colp = eidx + nnz;

    k_fused<<<FUSE_NB, 256>>>(inlayer, dual, conv_w, conv_b, rowp, erel, nnz);
    k_sort<<<SORT_NB, 256>>>(rowp, colp, erel, nnz, out);

    const int nwarps = (nnz + Q - 1) / Q;                 // 12500
    k_gather<<<(nwarps * 32 + 127) / 128, 128>>>(out, nnz);
}

// round 15
// speedup vs baseline: 1.2219x; 1.2219x over previous
#include <cuda_runtime.h>
#include <cuda_fp16.h>

#define N_NODES 50000
#define N_REL   1000
#define D       128
#define NNZ_MAX 800000

#define FUSE_NB  592          // fused kernel: 4 blocks/SM -> co-resident
#define SCAN_BLK 512
#define SCAN_NB  ((N_NODES + SCAN_BLK - 1) / SCAN_BLK)   // 98 co-resident blocks
#define Q        64           // edges per gather warp

// Scratch (allocation-free rule: __device__ globals)
__device__ float g_exp_lr[N_REL];
__device__ float g_coef[N_REL];           // exp / S
__device__ float g_S;
__device__ int   g_cnt[N_NODES];
__device__ int   g_bsum[SCAN_NB];
__device__ int   g_tick1;                 // ticket barrier (fused, 592-wide)
__device__ int   g_tick2;                 // ticket barrier (scan, 98-wide)
__device__ int   g_offs[N_NODES + 1];
__device__ __align__(16) int g_rank[NNZ_MAX];
// 64-bit packed edge: coef_f32_bits<<32 | col<<16 | row
__device__ __align__(16) unsigned long long g_edges[NNZ_MAX];
__device__ __align__(16) __half g_inh[(size_t)N_NODES * D];   // fp16 features

// Monotonic ticket barrier (graph-replay-safe; boundaries are multiples of NBLK)
__device__ __forceinline__ void grid_bar(int* tick, int NBLK) {
    __syncthreads();
    __threadfence();
    if (threadIdx.x == 0) {
        const int t = atomicAdd(tick, 1);
        const int target = (t / NBLK + 1) * NBLK;
        while (atomicAdd(tick, 0) < target) {}
    }
    __syncthreads();
}

// ---------------------------------------------------------------------------
// K1 (fused): phase A: zero cnt/S + relation scores (warp/rel; shift=0 safe
//             by softmax shift-invariance with O(1) inputs)
//             -- bar(592) --
//             phase B: hist + per-edge rank + softmax denominator.
// (fp16 staging moved to K3 — only gather needs it.)
// ---------------------------------------------------------------------------
__global__ void __launch_bounds__(256, 4)
k_fused(const float* __restrict__ dual, const float* __restrict__ w,
        const float* __restrict__ b,
        const int* __restrict__ rowp, const int* __restrict__ relp, int nnz) {
    const int tid  = blockIdx.x * blockDim.x + threadIdx.x;
    const int nthr = FUSE_NB * 256;
    const int lane = threadIdx.x & 31;

    if (tid == 0) g_S = 0.f;
    for (int i = tid; i < N_NODES; i += nthr) g_cnt[i] = 0;

    const int r = tid >> 5;
    if (r < N_REL) {
        const float4 a  = reinterpret_cast<const float4*>(dual + (size_t)r * D)[lane];
        const float4 ww = reinterpret_cast<const float4*>(w)[lane];
        float s = a.x * ww.x + a.y * ww.y + a.z * ww.z + a.w * ww.w;
#pragma unroll
        for (int o = 16; o > 0; o >>= 1) s += __shfl_xor_sync(0xffffffffu, s, o);
        if (lane == 0) {
            s += b[0];
            const float lr = (s > 0.f) ? s : 0.01f * s;
            g_exp_lr[r] = expf(lr);
        }
    }

    grid_bar(&g_tick1, FUSE_NB);

    const int nvec = nnz >> 2;
    const int4* row4 = reinterpret_cast<const int4*>(rowp);
    const int4* rel4 = reinterpret_cast<const int4*>(relp);
    int4* rank4 = reinterpret_cast<int4*>(g_rank);

    float s = 0.f;
    for (int i = tid; i < nvec; i += nthr) {
        const int4 r0 = __ldg(row4 + i);
        const int4 q0 = __ldg(rel4 + i);
        int4 rk;
        rk.x = atomicAdd(&g_cnt[r0.x], 1);
        rk.y = atomicAdd(&g_cnt[r0.y], 1);
        rk.z = atomicAdd(&g_cnt[r0.z], 1);
        rk.w = atomicAdd(&g_cnt[r0.w], 1);
        rank4[i] = rk;
        s += g_exp_lr[q0.x] + g_exp_lr[q0.y] + g_exp_lr[q0.z] + g_exp_lr[q0.w];
    }
    const int e0 = (nvec << 2) + tid;
    if (e0 < nnz) {
        g_rank[e0] = atomicAdd(&g_cnt[__ldg(rowp + e0)], 1);
        s += g_exp_lr[__ldg(relp + e0)];
    }
#pragma unroll
    for (int o = 16; o > 0; o >>= 1) s += __shfl_xor_sync(0xffffffffu, s, o);
    __shared__ float smf[8];
    if ((threadIdx.x & 31) == 0) smf[threadIdx.x >> 5] = s;
    __syncthreads();
    if (threadIdx.x < 32) {
        float v = (threadIdx.x < 8) ? smf[threadIdx.x] : 0.f;
#pragma unroll
        for (int o = 4; o > 0; o >>= 1) v += __shfl_xor_sync(0xffffffffu, v, o);
        if (threadIdx.x == 0) atomicAdd(&g_S, v);
    }
}

// ---------------------------------------------------------------------------
// K2: scan (98 co-resident blocks). Block 0 normalizes coef. After the
// barrier, each thread also zero-flags its row inline (off/v in registers)
// and zeroes flagged output rows warp-cooperatively.
// ---------------------------------------------------------------------------
__global__ void __launch_bounds__(SCAN_BLK)
k_scan(int nnz, float* __restrict__ out) {
    __shared__ int sm[SCAN_BLK];
    const int t    = threadIdx.x;
    const int bid  = blockIdx.x;
    const int lane = t & 31;
    const int gid  = bid * SCAN_BLK + t;

    if (bid == 0) {
        const float invS = 1.0f / g_S;
        for (int r = t; r < N_REL; r += SCAN_BLK) g_coef[r] = g_exp_lr[r] * invS;
    }

    const int v = (gid < N_NODES) ? g_cnt[gid] : 0;
    sm[t] = v;
    __syncthreads();
#pragma unroll
    for (int o = 1; o < SCAN_BLK; o <<= 1) {
        const int p = (t >= o) ? sm[t - o] : 0;
        __syncthreads();
        sm[t] += p;
        __syncthreads();
    }
    const int incl = sm[t];
    if (t == SCAN_BLK - 1) g_bsum[bid] = incl;

    grid_bar(&g_tick2, SCAN_NB);

    sm[t] = (t < bid) ? g_bsum[t] : 0;
    __syncthreads();
#pragma unroll
    for (int o = SCAN_BLK / 2; o > 0; o >>= 1) {
        if (t < o) sm[t] += sm[t + o];
        __syncthreads();
    }
    const int base = sm[0];
    const int off  = base + incl - v;
    const bool valid = (gid < N_NODES);

    if (valid) g_offs[gid] = off;
    if (gid == N_NODES - 1) g_offs[N_NODES] = nnz;

    // zero-flag: rows the balanced gather hits with atomics (or empty rows)
    const int en = off + v;
    bool flag = false;
    if (valid)
        flag = (v == 0) || (off % Q == 0) || (en % Q == 0) ||
               (en == nnz) || ((off / Q) != ((en - 1) / Q));
    unsigned m = __ballot_sync(0xffffffffu, flag);
    const int wbase = gid - lane;
    while (m) {
        const int j = __ffs(m) - 1;
        m &= m - 1;
        reinterpret_cast<float4*>(out + (size_t)(wbase + j) * D)[lane] =
            make_float4(0.f, 0.f, 0.f, 0.f);
    }
}

// ---------------------------------------------------------------------------
// K3: reorder into 64-bit packed edges (coef folded; pos = offs[row] + rank,
// no atomics), 8 edges/thread — PLUS the fp16 staging stream, interleaved to
// overlap reorder's scatter latency with pure bandwidth work.
// ---------------------------------------------------------------------------
__global__ void __launch_bounds__(256)
k_reorder(const int* __restrict__ rowp, const int* __restrict__ colp,
          const int* __restrict__ relp, int nnz,
          const float* __restrict__ inlayer) {
    const int nvec = nnz >> 2;
    const int tid  = blockIdx.x * blockDim.x + threadIdx.x;
    const int nthr = gridDim.x * blockDim.x;

#pragma unroll
    for (int k = 0; k < 2; k++) {
        const int i = tid * 2 + k;
        if (i < nvec) {
            const int4 r  = __ldg(reinterpret_cast<const int4*>(rowp) + i);
            const int4 c  = __ldg(reinterpret_cast<const int4*>(colp) + i);
            const int4 q  = __ldg(reinterpret_cast<const int4*>(relp) + i);
            const int4 rk = __ldg(reinterpret_cast<const int4*>(g_rank) + i);
            const int p0 = __ldg(&g_offs[r.x]) + rk.x;
            const int p1 = __ldg(&g_offs[r.y]) + rk.y;
            const int p2 = __ldg(&g_offs[r.z]) + rk.z;
            const int p3 = __ldg(&g_offs[r.w]) + rk.w;
            const unsigned cf0 = __float_as_uint(__ldg(&g_coef[q.x]));
            const unsigned cf1 = __float_as_uint(__ldg(&g_coef[q.y]));
            const unsigned cf2 = __float_as_uint(__ldg(&g_coef[q.z]));
            const unsigned cf3 = __float_as_uint(__ldg(&g_coef[q.w]));
            g_edges[p0] = ((unsigned long long)cf0 << 32) | ((unsigned)c.x << 16) | (unsigned)r.x;
            g_edges[p1] = ((unsigned long long)cf1 << 32) | ((unsigned)c.y << 16) | (unsigned)r.y;
            g_edges[p2] = ((unsigned long long)cf2 << 32) | ((unsigned)c.z << 16) | (unsigned)r.z;
            g_edges[p3] = ((unsigned long long)cf3 << 32) | ((unsigned)c.w << 16) | (unsigned)r.w;
        }
    }
    const int e = (nvec << 2) + tid;
    if (e < nnz) {
        const int row = __ldg(rowp + e);
        const int pos = __ldg(&g_offs[row]) + g_rank[e];
        const unsigned cf = __float_as_uint(__ldg(&g_coef[__ldg(relp + e)]));
        g_edges[pos] = ((unsigned long long)cf << 32) |
                       ((unsigned)__ldg(colp + e) << 16) | (unsigned)row;
    }

    // fp16 staging (only gather consumes it): pure bandwidth stream that
    // overlaps the scatter-latency stalls above.
    const int nv = (N_NODES * D) / 4;
    const float4* in4 = reinterpret_cast<const float4*>(inlayer);
    uint2* out2 = reinterpret_cast<uint2*>(g_inh);
    for (int i = tid; i < nv; i += nthr) {
        const float4 v = __ldg(in4 + i);
        const __half2 h01 = __floats2half2_rn(v.x, v.y);
        const __half2 h23 = __floats2half2_rn(v.z, v.w);
        uint2 p;
        p.x = *reinterpret_cast<const unsigned*>(&h01);
        p.y = *reinterpret_cast<const unsigned*>(&h23);
        out2[i] = p;
    }
}

// ---------------------------------------------------------------------------
// K4: balanced gather (byte-identical to R13's proven 26.6us version).
// ---------------------------------------------------------------------------
__device__ __forceinline__ void acc_edge_cvt(uint2 hv, float c, float4& a) {
    const float2 f01 = __half22float2(*reinterpret_cast<const __half2*>(&hv.x));
    const float2 f23 = __half22float2(*reinterpret_cast<const __half2*>(&hv.y));
    a.x = fmaf(c, f01.x, a.x);
    a.y = fmaf(c, f01.y, a.y);
    a.z = fmaf(c, f23.x, a.z);
    a.w = fmaf(c, f23.y, a.w);
}

__device__ __forceinline__ void flush_row(float* __restrict__ out, int row,
                                          const float4& a, bool atomic, int lane) {
    float* p = out + (size_t)row * D + lane * 4;
    if (atomic) {
        asm volatile("red.global.add.v4.f32 [%0], {%1, %2, %3, %4};"
                     :: "l"(p), "f"(a.x), "f"(a.y), "f"(a.z), "f"(a.w)
                     : "memory");
    } else {
        *reinterpret_cast<float4*>(p) = a;
    }
}

__global__ void __launch_bounds__(128)
k_gather(float* __restrict__ out, int nnz) {
    const int lane = threadIdx.x & 31;
    const int wid  = (blockIdx.x * blockDim.x + threadIdx.x) >> 5;
    const int base = wid * Q;
    if (base >= nnz) return;
    const int end = min(base + Q, nnz);

    int   currow = (int)((unsigned)__ldg(&g_edges[base]) & 0xFFFFu);
    bool  first  = true;
    float4 acc   = make_float4(0.f, 0.f, 0.f, 0.f);

    int i = base;
    for (; i + 3 < end; i += 4) {
        const ulonglong2 ea = __ldg(reinterpret_cast<const ulonglong2*>(g_edges + i));
        const ulonglong2 eb = __ldg(reinterpret_cast<const ulonglong2*>(g_edges + i + 2));
        const uint2 v0 = __ldg(reinterpret_cast<const uint2*>(
                g_inh + (size_t)((unsigned)(ea.x >> 16) & 0xFFFFu) * D) + lane);
        const uint2 v1 = __ldg(reinterpret_cast<const uint2*>(
                g_inh + (size_t)((unsigned)(ea.y >> 16) & 0xFFFFu) * D) + lane);
        const uint2 v2 = __ldg(reinterpret_cast<const uint2*>(
                g_inh + (size_t)((unsigned)(eb.x >> 16) & 0xFFFFu) * D) + lane);
        const uint2 v3 = __ldg(reinterpret_cast<const uint2*>(
                g_inh + (size_t)((unsigned)(eb.y >> 16) & 0xFFFFu) * D) + lane);

        const unsigned long long eds[4] = {ea.x, ea.y, eb.x, eb.y};
        const uint2 vs[4] = {v0, v1, v2, v3};
#pragma unroll
        for (int k = 0; k < 4; k++) {
            const int row = (int)((unsigned)eds[k] & 0xFFFFu);
            if (row != currow) {
                flush_row(out, currow, acc, first, lane);
                first = false;
                acc = make_float4(0.f, 0.f, 0.f, 0.f);
                currow = row;
            }
            const float c = __uint_as_float((unsigned)(eds[k] >> 32));
            acc_edge_cvt(vs[k], c, acc);
        }
    }
    for (; i < end; i++) {
        const unsigned long long ed = __ldg(&g_edges[i]);
        const int row = (int)((unsigned)ed & 0xFFFFu);
        if (row != currow) {
            flush_row(out, currow, acc, first, lane);
            first = false;
            acc = make_float4(0.f, 0.f, 0.f, 0.f);
            currow = row;
        }
        const uint2 v = __ldg(reinterpret_cast<const uint2*>(
                g_inh + (size_t)((unsigned)(ed >> 16) & 0xFFFFu) * D) + lane);
        const float c = __uint_as_float((unsigned)(ed >> 32));
        acc_edge_cvt(v, c, acc);
    }
    flush_row(out, currow, acc, true, lane);
}

// ---------------------------------------------------------------------------
// kernel_launch
// Inputs: 0 inlayer [N,D] f32 | 1 dual [R,D] f32 | 2 conv_w [D] f32
//         3 conv_b [1] f32    | 4 edge_idx [2,NNZ] i32 | 5 edge_rel [NNZ] i32
// Output: [N, D] f32
// ---------------------------------------------------------------------------
extern "C" void kernel_launch(void* const* d_in, const int* in_sizes, int n_in,
                              void* d_out, int out_size) {
    const float* inlayer = (const float*)d_in[0];
    const float* dual    = (const float*)d_in[1];
    const float* conv_w  = (const float*)d_in[2];
    const float* conv_b  = (const float*)d_in[3];
    const int*   eidx    = (const int*)d_in[4];
    const int*   erel    = (const int*)d_in[5];
    float*       out     = (float*)d_out;

    const int nnz = in_sizes[5];
    const int* rowp = eidx;
    const int* colp = eidx + nnz;

    k_fused<<<FUSE_NB, 256>>>(dual, conv_w, conv_b, rowp, erel, nnz);
    k_scan<<<SCAN_NB, SCAN_BLK>>>(nnz, out);
    k_reorder<<<(nnz / 8 + 255) / 256, 256>>>(rowp, colp, erel, nnz, inlayer);

    const int nwarps = (nnz + Q - 1) / Q;                 // 12500
    k_gather<<<(nwarps * 32 + 127) / 128, 128>>>(out, nnz);
}

// round 16
// speedup vs baseline: 1.2461x; 1.0198x over previous
#include <cuda_runtime.h>
#include <cuda_fp16.h>

#define N_NODES 50000
#define N_REL   1000
#define D       128
#define NNZ_MAX 800000

#define FUSE_NB  592          // fused kernel: 4 blocks/SM -> co-resident
#define SCAN_BLK 512
#define SCAN_NB  ((N_NODES + SCAN_BLK - 1) / SCAN_BLK)   // 98 co-resident blocks
#define Q        64           // edges per gather warp

// Scratch (allocation-free rule: __device__ globals)
__device__ float g_exp_lr[N_REL];
__device__ float g_coef[N_REL];           // exp / S
__device__ float g_S;
__device__ int   g_cnt[N_NODES];
__device__ int   g_bsum[SCAN_NB];
__device__ int   g_tick1;                 // ticket barrier (fused, 592-wide)
__device__ int   g_tick2;                 // ticket barrier (scan, 98-wide)
__device__ int   g_offs[N_NODES + 1];
__device__ __align__(16) int g_rank[NNZ_MAX];
// 64-bit packed edge: coef_f32_bits<<32 | col<<16 | row
__device__ __align__(16) unsigned long long g_edges[NNZ_MAX];
__device__ __align__(16) __half g_inh[(size_t)N_NODES * D];   // fp16 features

// Monotonic ticket barrier (graph-replay-safe; boundaries are multiples of NBLK)
__device__ __forceinline__ void grid_bar(int* tick, int NBLK) {
    __syncthreads();
    __threadfence();
    if (threadIdx.x == 0) {
        const int t = atomicAdd(tick, 1);
        const int target = (t / NBLK + 1) * NBLK;
        while (atomicAdd(tick, 0) < target) {}
    }
    __syncthreads();
}

// ---------------------------------------------------------------------------
// K1 (fused, R13-identical): phase A: zero cnt/S + relation scores
//             -- bar(592) --
//             phase B: hist + rank + denominator, then fp16 staging.
// ---------------------------------------------------------------------------
__global__ void __launch_bounds__(256, 4)
k_fused(const float* __restrict__ inlayer, const float* __restrict__ dual,
        const float* __restrict__ w, const float* __restrict__ b,
        const int* __restrict__ rowp, const int* __restrict__ relp, int nnz) {
    const int tid  = blockIdx.x * blockDim.x + threadIdx.x;
    const int nthr = FUSE_NB * 256;
    const int lane = threadIdx.x & 31;

    if (tid == 0) g_S = 0.f;
    for (int i = tid; i < N_NODES; i += nthr) g_cnt[i] = 0;

    const int r = tid >> 5;
    if (r < N_REL) {
        const float4 a  = reinterpret_cast<const float4*>(dual + (size_t)r * D)[lane];
        const float4 ww = reinterpret_cast<const float4*>(w)[lane];
        float s = a.x * ww.x + a.y * ww.y + a.z * ww.z + a.w * ww.w;
#pragma unroll
        for (int o = 16; o > 0; o >>= 1) s += __shfl_xor_sync(0xffffffffu, s, o);
        if (lane == 0) {
            s += b[0];
            const float lr = (s > 0.f) ? s : 0.01f * s;
            g_exp_lr[r] = expf(lr);
        }
    }

    grid_bar(&g_tick1, FUSE_NB);

    const int nvec = nnz >> 2;
    {
        const int4* row4 = reinterpret_cast<const int4*>(rowp);
        const int4* rel4 = reinterpret_cast<const int4*>(relp);
        int4* rank4 = reinterpret_cast<int4*>(g_rank);

        float s = 0.f;
        for (int i = tid; i < nvec; i += nthr) {
            const int4 r0 = __ldg(row4 + i);
            const int4 q0 = __ldg(rel4 + i);
            int4 rk;
            rk.x = atomicAdd(&g_cnt[r0.x], 1);
            rk.y = atomicAdd(&g_cnt[r0.y], 1);
            rk.z = atomicAdd(&g_cnt[r0.z], 1);
            rk.w = atomicAdd(&g_cnt[r0.w], 1);
            rank4[i] = rk;
            s += g_exp_lr[q0.x] + g_exp_lr[q0.y] + g_exp_lr[q0.z] + g_exp_lr[q0.w];
        }
        const int e0 = (nvec << 2) + tid;
        if (e0 < nnz) {
            g_rank[e0] = atomicAdd(&g_cnt[__ldg(rowp + e0)], 1);
            s += g_exp_lr[__ldg(relp + e0)];
        }
#pragma unroll
        for (int o = 16; o > 0; o >>= 1) s += __shfl_xor_sync(0xffffffffu, s, o);
        __shared__ float smf[8];
        if ((threadIdx.x & 31) == 0) smf[threadIdx.x >> 5] = s;
        __syncthreads();
        if (threadIdx.x < 32) {
            float v = (threadIdx.x < 8) ? smf[threadIdx.x] : 0.f;
#pragma unroll
            for (int o = 4; o > 0; o >>= 1) v += __shfl_xor_sync(0xffffffffu, v, o);
            if (threadIdx.x == 0) atomicAdd(&g_S, v);
        }
    }

    {   // fp16 staging
        const int nv = (N_NODES * D) / 4;
        const float4* in4 = reinterpret_cast<const float4*>(inlayer);
        uint2* out2 = reinterpret_cast<uint2*>(g_inh);
        for (int i = tid; i < nv; i += nthr) {
            const float4 v = __ldg(in4 + i);
            const __half2 h01 = __floats2half2_rn(v.x, v.y);
            const __half2 h23 = __floats2half2_rn(v.z, v.w);
            uint2 p;
            p.x = *reinterpret_cast<const unsigned*>(&h01);
            p.y = *reinterpret_cast<const unsigned*>(&h23);
            out2[i] = p;
        }
    }
}

// ---------------------------------------------------------------------------
// K2: scan (R13-identical).
// ---------------------------------------------------------------------------
__global__ void __launch_bounds__(SCAN_BLK)
k_scan(int nnz) {
    __shared__ int sm[SCAN_BLK];
    const int t   = threadIdx.x;
    const int bid = blockIdx.x;
    const int gid = bid * SCAN_BLK + t;

    if (bid == 0) {
        const float invS = 1.0f / g_S;
        for (int r = t; r < N_REL; r += SCAN_BLK) g_coef[r] = g_exp_lr[r] * invS;
    }

    const int v = (gid < N_NODES) ? g_cnt[gid] : 0;
    sm[t] = v;
    __syncthreads();
#pragma unroll
    for (int o = 1; o < SCAN_BLK; o <<= 1) {
        const int p = (t >= o) ? sm[t - o] : 0;
        __syncthreads();
        sm[t] += p;
        __syncthreads();
    }
    const int incl = sm[t];
    if (t == SCAN_BLK - 1) g_bsum[bid] = incl;

    grid_bar(&g_tick2, SCAN_NB);

    sm[t] = (t < bid) ? g_bsum[t] : 0;
    __syncthreads();
#pragma unroll
    for (int o = SCAN_BLK / 2; o > 0; o >>= 1) {
        if (t < o) sm[t] += sm[t + o];
        __syncthreads();
    }
    const int base = sm[0];

    if (gid < N_NODES) g_offs[gid] = base + incl - v;
    if (gid == N_NODES - 1) g_offs[N_NODES] = nnz;
}

// ---------------------------------------------------------------------------
// K3: reorder (R13-identical): 64-bit packed edges + zero-flag pass.
// ---------------------------------------------------------------------------
__global__ void __launch_bounds__(256)
k_reorder(const int* __restrict__ rowp, const int* __restrict__ colp,
          const int* __restrict__ relp, int nnz, float* __restrict__ out) {
    const int nvec = nnz >> 2;
    const int tid  = blockIdx.x * blockDim.x + threadIdx.x;
    const int lane = threadIdx.x & 31;

#pragma unroll
    for (int k = 0; k < 2; k++) {
        const int i = tid * 2 + k;
        if (i < nvec) {
            const int4 r  = __ldg(reinterpret_cast<const int4*>(rowp) + i);
            const int4 c  = __ldg(reinterpret_cast<const int4*>(colp) + i);
            const int4 q  = __ldg(reinterpret_cast<const int4*>(relp) + i);
            const int4 rk = __ldg(reinterpret_cast<const int4*>(g_rank) + i);
            const int p0 = __ldg(&g_offs[r.x]) + rk.x;
            const int p1 = __ldg(&g_offs[r.y]) + rk.y;
            const int p2 = __ldg(&g_offs[r.z]) + rk.z;
            const int p3 = __ldg(&g_offs[r.w]) + rk.w;
            const unsigned cf0 = __float_as_uint(__ldg(&g_coef[q.x]));
            const unsigned cf1 = __float_as_uint(__ldg(&g_coef[q.y]));
            const unsigned cf2 = __float_as_uint(__ldg(&g_coef[q.z]));
            const unsigned cf3 = __float_as_uint(__ldg(&g_coef[q.w]));
            g_edges[p0] = ((unsigned long long)cf0 << 32) | ((unsigned)c.x << 16) | (unsigned)r.x;
            g_edges[p1] = ((unsigned long long)cf1 << 32) | ((unsigned)c.y << 16) | (unsigned)r.y;
            g_edges[p2] = ((unsigned long long)cf2 << 32) | ((unsigned)c.z << 16) | (unsigned)r.z;
            g_edges[p3] = ((unsigned long long)cf3 << 32) | ((unsigned)c.w << 16) | (unsigned)r.w;
        }
    }
    const int e = (nvec << 2) + tid;
    if (e < nnz) {
        const int row = __ldg(rowp + e);
        const int pos = __ldg(&g_offs[row]) + g_rank[e];
        const unsigned cf = __float_as_uint(__ldg(&g_coef[__ldg(relp + e)]));
        g_edges[pos] = ((unsigned long long)cf << 32) |
                       ((unsigned)__ldg(colp + e) << 16) | (unsigned)row;
    }

    // pre-zero atomic-candidate rows (quota-boundary / empty)
    const int wglob  = (blockIdx.x * blockDim.x + threadIdx.x) >> 5;
    const int nwarps = (gridDim.x * blockDim.x) >> 5;
    for (int rrow = wglob; rrow < N_NODES; rrow += nwarps) {
        const int s  = __ldg(&g_offs[rrow]);
        const int en = __ldg(&g_offs[rrow + 1]);
        const bool flag = (s == en) || (s % Q == 0) || (en % Q == 0) ||
                          (en == nnz) || ((s / Q) != ((en - 1) / Q));
        if (flag)
            reinterpret_cast<float4*>(out + (size_t)rrow * D)[lane] =
                make_float4(0.f, 0.f, 0.f, 0.f);
    }
}

// ---------------------------------------------------------------------------
// K4: balanced gather, 8-edge chunks (was 4). 4x LDG.128 streamed edge loads
// (__ldcs: read-once, keep L1 for features) + 8 independent feature gathers
// in flight. F2F converts on the convert pipe; interior rows -> float4 store;
// boundary rows -> RED.v4 (pre-zeroed).
// ---------------------------------------------------------------------------
__device__ __forceinline__ void acc_edge_cvt(uint2 hv, float c, float4& a) {
    const float2 f01 = __half22float2(*reinterpret_cast<const __half2*>(&hv.x));
    const float2 f23 = __half22float2(*reinterpret_cast<const __half2*>(&hv.y));
    a.x = fmaf(c, f01.x, a.x);
    a.y = fmaf(c, f01.y, a.y);
    a.z = fmaf(c, f23.x, a.z);
    a.w = fmaf(c, f23.y, a.w);
}

__device__ __forceinline__ void flush_row(float* __restrict__ out, int row,
                                          const float4& a, bool atomic, int lane) {
    float* p = out + (size_t)row * D + lane * 4;
    if (atomic) {
        asm volatile("red.global.add.v4.f32 [%0], {%1, %2, %3, %4};"
                     :: "l"(p), "f"(a.x), "f"(a.y), "f"(a.z), "f"(a.w)
                     : "memory");
    } else {
        *reinterpret_cast<float4*>(p) = a;
    }
}

__global__ void __launch_bounds__(128)
k_gather(float* __restrict__ out, int nnz) {
    const int lane = threadIdx.x & 31;
    const int wid  = (blockIdx.x * blockDim.x + threadIdx.x) >> 5;
    const int base = wid * Q;
    if (base >= nnz) return;
    const int end = min(base + Q, nnz);

    int   currow = (int)((unsigned)__ldg(&g_edges[base]) & 0xFFFFu);
    bool  first  = true;
    float4 acc   = make_float4(0.f, 0.f, 0.f, 0.f);

    int i = base;
    for (; i + 7 < end; i += 8) {
        const ulonglong2 ea = __ldcs(reinterpret_cast<const ulonglong2*>(g_edges + i));
        const ulonglong2 eb = __ldcs(reinterpret_cast<const ulonglong2*>(g_edges + i + 2));
        const ulonglong2 ec = __ldcs(reinterpret_cast<const ulonglong2*>(g_edges + i + 4));
        const ulonglong2 ed = __ldcs(reinterpret_cast<const ulonglong2*>(g_edges + i + 6));

        const unsigned long long eds[8] = {ea.x, ea.y, eb.x, eb.y,
                                           ec.x, ec.y, ed.x, ed.y};
        uint2 vs[8];
#pragma unroll
        for (int k = 0; k < 8; k++) {
            vs[k] = __ldg(reinterpret_cast<const uint2*>(
                g_inh + (size_t)((unsigned)(eds[k] >> 16) & 0xFFFFu) * D) + lane);
        }
#pragma unroll
        for (int k = 0; k < 8; k++) {
            const int row = (int)((unsigned)eds[k] & 0xFFFFu);
            if (row != currow) {
                flush_row(out, currow, acc, first, lane);
                first = false;
                acc = make_float4(0.f, 0.f, 0.f, 0.f);
                currow = row;
            }
            const float c = __uint_as_float((unsigned)(eds[k] >> 32));
            acc_edge_cvt(vs[k], c, acc);
        }
    }
    for (; i < end; i++) {
        const unsigned long long ed = __ldg(&g_edges[i]);
        const int row = (int)((unsigned)ed & 0xFFFFu);
        if (row != currow) {
            flush_row(out, currow, acc, first, lane);
            first = false;
            acc = make_float4(0.f, 0.f, 0.f, 0.f);
            currow = row;
        }
        const uint2 v = __ldg(reinterpret_cast<const uint2*>(
                g_inh + (size_t)((unsigned)(ed >> 16) & 0xFFFFu) * D) + lane);
        const float c = __uint_as_float((unsigned)(ed >> 32));
        acc_edge_cvt(v, c, acc);
    }
    flush_row(out, currow, acc, true, lane);
}

// ---------------------------------------------------------------------------
// kernel_launch
// Inputs: 0 inlayer [N,D] f32 | 1 dual [R,D] f32 | 2 conv_w [D] f32
//         3 conv_b [1] f32    | 4 edge_idx [2,NNZ] i32 | 5 edge_rel [NNZ] i32
// Output: [N, D] f32
// ---------------------------------------------------------------------------
extern "C" void kernel_launch(void* const* d_in, const int* in_sizes, int n_in,
                              void* d_out, int out_size) {
    const float* inlayer = (const float*)d_in[0];
    const float* dual    = (const float*)d_in[1];
    const float* conv_w  = (const float*)d_in[2];
    const float* conv_b  = (const float*)d_in[3];
    const int*   eidx    = (const int*)d_in[4];
    const int*   erel    = (const int*)d_in[5];
    float*       out     = (float*)d_out;

    const int nnz = in_sizes[5];
    const int* rowp = eidx;
    const int* colp = eidx + nnz;

    k_fused<<<FUSE_NB, 256>>>(inlayer, dual, conv_w, conv_b, rowp, erel, nnz);
    k_scan<<<SCAN_NB, SCAN_BLK>>>(nnz);
    k_reorder<<<(nnz / 8 + 255) / 256, 256>>>(rowp, colp, erel, nnz, out);

    const int nwarps = (nnz + Q - 1) / Q;                 // 12500
    k_gather<<<(nwarps * 32 + 127) / 128, 128>>>(out, nnz);
}

// round 17
// speedup vs baseline: 1.2517x; 1.0044x over previous
#include <cuda_runtime.h>
#include <cuda_fp16.h>

#define N_NODES 50000
#define N_REL   1000
#define D       128
#define NNZ_MAX 800000

#define FUSE_NB  592          // fused kernel: 4 blocks/SM -> co-resident
#define SCAN_BLK 512
#define SCAN_NB  ((N_NODES + SCAN_BLK - 1) / SCAN_BLK)   // 98 co-resident blocks
#define Q        64           // edges per gather warp

// Scratch (allocation-free rule: __device__ globals)
__device__ float g_exp_lr[N_REL];
__device__ float g_coef[N_REL];           // exp / S
__device__ float g_S;
__device__ int   g_cnt[N_NODES];
__device__ int   g_bsum[SCAN_NB];
__device__ int   g_tick1;                 // ticket barrier (fused, 592-wide)
__device__ int   g_tick2;                 // ticket barrier (scan, 98-wide)
__device__ int   g_offs[N_NODES + 1];
__device__ __align__(16) int g_rank[NNZ_MAX];
// 64-bit packed edge: coef_f32_bits<<32 | col<<16 | row
__device__ __align__(16) unsigned long long g_edges[NNZ_MAX];
__device__ __align__(16) __half g_inh[(size_t)N_NODES * D];   // fp16 features

// Monotonic ticket barrier (graph-replay-safe; boundaries are multiples of NBLK)
__device__ __forceinline__ void grid_bar(int* tick, int NBLK) {
    __syncthreads();
    __threadfence();
    if (threadIdx.x == 0) {
        const int t = atomicAdd(tick, 1);
        const int target = (t / NBLK + 1) * NBLK;
        while (atomicAdd(tick, 0) < target) {}
    }
    __syncthreads();
}

// ---------------------------------------------------------------------------
// K1 (fused): phase A: zero cnt/S + relation scores (warp/rel; shift=0 safe)
//             -- bar(592) --
//             phase B: hist + rank + denominator, then fp16 staging with
//             4-deep MLP (4 independent float4 loads in flight).
// ---------------------------------------------------------------------------
__global__ void __launch_bounds__(256, 4)
k_fused(const float* __restrict__ inlayer, const float* __restrict__ dual,
        const float* __restrict__ w, const float* __restrict__ b,
        const int* __restrict__ rowp, const int* __restrict__ relp, int nnz) {
    const int tid  = blockIdx.x * blockDim.x + threadIdx.x;
    const int nthr = FUSE_NB * 256;
    const int lane = threadIdx.x & 31;

    if (tid == 0) g_S = 0.f;
    for (int i = tid; i < N_NODES; i += nthr) g_cnt[i] = 0;

    const int r = tid >> 5;
    if (r < N_REL) {
        const float4 a  = reinterpret_cast<const float4*>(dual + (size_t)r * D)[lane];
        const float4 ww = reinterpret_cast<const float4*>(w)[lane];
        float s = a.x * ww.x + a.y * ww.y + a.z * ww.z + a.w * ww.w;
#pragma unroll
        for (int o = 16; o > 0; o >>= 1) s += __shfl_xor_sync(0xffffffffu, s, o);
        if (lane == 0) {
            s += b[0];
            const float lr = (s > 0.f) ? s : 0.01f * s;
            g_exp_lr[r] = expf(lr);
        }
    }

    grid_bar(&g_tick1, FUSE_NB);

    // ---- phase B: histogram + rank + denominator ----
    const int nvec = nnz >> 2;
    {
        const int4* row4 = reinterpret_cast<const int4*>(rowp);
        const int4* rel4 = reinterpret_cast<const int4*>(relp);
        int4* rank4 = reinterpret_cast<int4*>(g_rank);

        float s = 0.f;
        for (int i = tid; i < nvec; i += nthr) {
            const int4 r0 = __ldg(row4 + i);
            const int4 q0 = __ldg(rel4 + i);
            int4 rk;
            rk.x = atomicAdd(&g_cnt[r0.x], 1);
            rk.y = atomicAdd(&g_cnt[r0.y], 1);
            rk.z = atomicAdd(&g_cnt[r0.z], 1);
            rk.w = atomicAdd(&g_cnt[r0.w], 1);
            rank4[i] = rk;
            s += g_exp_lr[q0.x] + g_exp_lr[q0.y] + g_exp_lr[q0.z] + g_exp_lr[q0.w];
        }
        const int e0 = (nvec << 2) + tid;
        if (e0 < nnz) {
            g_rank[e0] = atomicAdd(&g_cnt[__ldg(rowp + e0)], 1);
            s += g_exp_lr[__ldg(relp + e0)];
        }
#pragma unroll
        for (int o = 16; o > 0; o >>= 1) s += __shfl_xor_sync(0xffffffffu, s, o);
        __shared__ float smf[8];
        if ((threadIdx.x & 31) == 0) smf[threadIdx.x >> 5] = s;
        __syncthreads();
        if (threadIdx.x < 32) {
            float v = (threadIdx.x < 8) ? smf[threadIdx.x] : 0.f;
#pragma unroll
            for (int o = 4; o > 0; o >>= 1) v += __shfl_xor_sync(0xffffffffu, v, o);
            if (threadIdx.x == 0) atomicAdd(&g_S, v);
        }
    }

    // ---- phase B (cont.): fp16 staging, 4 loads in flight per iteration ----
    {
        const int nv = (N_NODES * D) / 4;          // 1.6M float4
        const float4* in4 = reinterpret_cast<const float4*>(inlayer);
        uint2* out2 = reinterpret_cast<uint2*>(g_inh);
        int i = tid;
        const int stride = nthr;
        for (; i + 3 * stride < nv; i += 4 * stride) {
            const float4 v0 = __ldg(in4 + i);
            const float4 v1 = __ldg(in4 + i + stride);
            const float4 v2 = __ldg(in4 + i + 2 * stride);
            const float4 v3 = __ldg(in4 + i + 3 * stride);
            uint2 p0, p1, p2, p3;
            { const __half2 a = __floats2half2_rn(v0.x, v0.y), c = __floats2half2_rn(v0.z, v0.w);
              p0.x = *reinterpret_cast<const unsigned*>(&a); p0.y = *reinterpret_cast<const unsigned*>(&c); }
            { const __half2 a = __floats2half2_rn(v1.x, v1.y), c = __floats2half2_rn(v1.z, v1.w);
              p1.x = *reinterpret_cast<const unsigned*>(&a); p1.y = *reinterpret_cast<const unsigned*>(&c); }
            { const __half2 a = __floats2half2_rn(v2.x, v2.y), c = __floats2half2_rn(v2.z, v2.w);
              p2.x = *reinterpret_cast<const unsigned*>(&a); p2.y = *reinterpret_cast<const unsigned*>(&c); }
            { const __half2 a = __floats2half2_rn(v3.x, v3.y), c = __floats2half2_rn(v3.z, v3.w);
              p3.x = *reinterpret_cast<const unsigned*>(&a); p3.y = *reinterpret_cast<const unsigned*>(&c); }
            out2[i] = p0;
            out2[i + stride] = p1;
            out2[i + 2 * stride] = p2;
            out2[i + 3 * stride] = p3;
        }
        for (; i < nv; i += stride) {
            const float4 v = __ldg(in4 + i);
            const __half2 h01 = __floats2half2_rn(v.x, v.y);
            const __half2 h23 = __floats2half2_rn(v.z, v.w);
            uint2 p;
            p.x = *reinterpret_cast<const unsigned*>(&h01);
            p.y = *reinterpret_cast<const unsigned*>(&h23);
            out2[i] = p;
        }
    }
}

// ---------------------------------------------------------------------------
// K2: scan with warp-shuffle scans (4 __syncthreads total vs 27).
// Block 0 normalizes coef. Monotonic barrier between phases.
// ---------------------------------------------------------------------------
__global__ void __launch_bounds__(SCAN_BLK)
k_scan(int nnz) {
    __shared__ int smw[16];       // warp totals
    __shared__ int sred[16];      // base-reduction partials
    const int t    = threadIdx.x;
    const int bid  = blockIdx.x;
    const int lane = t & 31;
    const int wrp  = t >> 5;      // 16 warps
    const int gid  = bid * SCAN_BLK + t;

    if (bid == 0) {
        const float invS = 1.0f / g_S;
        for (int r = t; r < N_REL; r += SCAN_BLK) g_coef[r] = g_exp_lr[r] * invS;
    }

    const int v = (gid < N_NODES) ? g_cnt[gid] : 0;

    // warp-inclusive scan
    int run = v;
#pragma unroll
    for (int o = 1; o < 32; o <<= 1) {
        const int n = __shfl_up_sync(0xffffffffu, run, o);
        if (lane >= o) run += n;
    }
    if (lane == 31) smw[wrp] = run;
    __syncthreads();
    // warp 0 scans the 16 warp totals
    if (wrp == 0 && lane < 16) {
        int wv = smw[lane];
#pragma unroll
        for (int o = 1; o < 16; o <<= 1) {
            const int n = __shfl_up_sync(0x0000ffffu, wv, o);
            if (lane >= o) wv += n;
        }
        smw[lane] = wv;
    }
    __syncthreads();
    const int incl = run + (wrp > 0 ? smw[wrp - 1] : 0);
    if (t == SCAN_BLK - 1) g_bsum[bid] = incl;

    grid_bar(&g_tick2, SCAN_NB);

    // block base = sum of predecessors' totals (98 values, warp-reduced)
    {
        int pv = 0;
        if (t < SCAN_NB && t < bid) pv = g_bsum[t];
        if (t < 128) {                          // 4 warps cover 98 entries
#pragma unroll
            for (int o = 16; o > 0; o >>= 1) pv += __shfl_xor_sync(0xffffffffu, pv, o);
            if (lane == 0) sred[wrp] = pv;
        }
        __syncthreads();
        if (t == 0) sred[0] = sred[0] + sred[1] + sred[2] + sred[3];
        __syncthreads();
    }
    const int base = sred[0];

    if (gid < N_NODES) g_offs[gid] = base + incl - v;
    if (gid == N_NODES - 1) g_offs[N_NODES] = nnz;
}

// ---------------------------------------------------------------------------
// K3: reorder — all loads batched before all stores (max MLP), 8 edges/thread,
// plus the zero-flag pass for atomic-candidate output rows.
// ---------------------------------------------------------------------------
__global__ void __launch_bounds__(256)
k_reorder(const int* __restrict__ rowp, const int* __restrict__ colp,
          const int* __restrict__ relp, int nnz, float* __restrict__ out) {
    const int nvec = nnz >> 2;
    const int tid  = blockIdx.x * blockDim.x + threadIdx.x;
    const int lane = threadIdx.x & 31;
    const int i0   = tid * 2;
    const int i1   = i0 + 1;

    if (i1 < nvec) {
        // batch ALL loads first
        const int4 rA  = __ldg(reinterpret_cast<const int4*>(rowp) + i0);
        const int4 rB  = __ldg(reinterpret_cast<const int4*>(rowp) + i1);
        const int4 cA  = __ldg(reinterpret_cast<const int4*>(colp) + i0);
        const int4 cB  = __ldg(reinterpret_cast<const int4*>(colp) + i1);
        const int4 qA  = __ldg(reinterpret_cast<const int4*>(relp) + i0);
        const int4 qB  = __ldg(reinterpret_cast<const int4*>(relp) + i1);
        const int4 kA  = __ldg(reinterpret_cast<const int4*>(g_rank) + i0);
        const int4 kB  = __ldg(reinterpret_cast<const int4*>(g_rank) + i1);
        // 8 independent offs gathers
        const int pA0 = __ldg(&g_offs[rA.x]) + kA.x;
        const int pA1 = __ldg(&g_offs[rA.y]) + kA.y;
        const int pA2 = __ldg(&g_offs[rA.z]) + kA.z;
        const int pA3 = __ldg(&g_offs[rA.w]) + kA.w;
        const int pB0 = __ldg(&g_offs[rB.x]) + kB.x;
        const int pB1 = __ldg(&g_offs[rB.y]) + kB.y;
        const int pB2 = __ldg(&g_offs[rB.z]) + kB.z;
        const int pB3 = __ldg(&g_offs[rB.w]) + kB.w;
        // 8 coef gathers (L1-hot table)
        const unsigned fA0 = __float_as_uint(g_coef[qA.x]);
        const unsigned fA1 = __float_as_uint(g_coef[qA.y]);
        const unsigned fA2 = __float_as_uint(g_coef[qA.z]);
        const unsigned fA3 = __float_as_uint(g_coef[qA.w]);
        const unsigned fB0 = __float_as_uint(g_coef[qB.x]);
        const unsigned fB1 = __float_as_uint(g_coef[qB.y]);
        const unsigned fB2 = __float_as_uint(g_coef[qB.z]);
        const unsigned fB3 = __float_as_uint(g_coef[qB.w]);
        // 8 scatter stores
        g_edges[pA0] = ((unsigned long long)fA0 << 32) | ((unsigned)cA.x << 16) | (unsigned)rA.x;
        g_edges[pA1] = ((unsigned long long)fA1 << 32) | ((unsigned)cA.y << 16) | (unsigned)rA.y;
        g_edges[pA2] = ((unsigned long long)fA2 << 32) | ((unsigned)cA.z << 16) | (unsigned)rA.z;
        g_edges[pA3] = ((unsigned long long)fA3 << 32) | ((unsigned)cA.w << 16) | (unsigned)rA.w;
        g_edges[pB0] = ((unsigned long long)fB0 << 32) | ((unsigned)cB.x << 16) | (unsigned)rB.x;
        g_edges[pB1] = ((unsigned long long)fB1 << 32) | ((unsigned)cB.y << 16) | (unsigned)rB.y;
        g_edges[pB2] = ((unsigned long long)fB2 << 32) | ((unsigned)cB.z << 16) | (unsigned)rB.z;
        g_edges[pB3] = ((unsigned long long)fB3 << 32) | ((unsigned)cB.w << 16) | (unsigned)rB.w;
    } else {
#pragma unroll
        for (int k = 0; k < 2; k++) {
            const int i = i0 + k;
            if (i < nvec) {
                const int4 r  = __ldg(reinterpret_cast<const int4*>(rowp) + i);
                const int4 c  = __ldg(reinterpret_cast<const int4*>(colp) + i);
                const int4 q  = __ldg(reinterpret_cast<const int4*>(relp) + i);
                const int4 rk = __ldg(reinterpret_cast<const int4*>(g_rank) + i);
                const int p0 = __ldg(&g_offs[r.x]) + rk.x;
                const int p1 = __ldg(&g_offs[r.y]) + rk.y;
                const int p2 = __ldg(&g_offs[r.z]) + rk.z;
                const int p3 = __ldg(&g_offs[r.w]) + rk.w;
                g_edges[p0] = ((unsigned long long)__float_as_uint(g_coef[q.x]) << 32) | ((unsigned)c.x << 16) | (unsigned)r.x;
                g_edges[p1] = ((unsigned long long)__float_as_uint(g_coef[q.y]) << 32) | ((unsigned)c.y << 16) | (unsigned)r.y;
                g_edges[p2] = ((unsigned long long)__float_as_uint(g_coef[q.z]) << 32) | ((unsigned)c.z << 16) | (unsigned)r.z;
                g_edges[p3] = ((unsigned long long)__float_as_uint(g_coef[q.w]) << 32) | ((unsigned)c.w << 16) | (unsigned)r.w;
            }
        }
    }
    const int e = (nvec << 2) + tid;
    if (e < nnz) {
        const int row = __ldg(rowp + e);
        const int pos = __ldg(&g_offs[row]) + g_rank[e];
        const unsigned cf = __float_as_uint(g_coef[__ldg(relp + e)]);
        g_edges[pos] = ((unsigned long long)cf << 32) |
                       ((unsigned)__ldg(colp + e) << 16) | (unsigned)row;
    }

    // pre-zero atomic-candidate rows (quota-boundary / empty)
    const int wglob  = (blockIdx.x * blockDim.x + threadIdx.x) >> 5;
    const int nwarps = (gridDim.x * blockDim.x) >> 5;
    for (int rrow = wglob; rrow < N_NODES; rrow += nwarps) {
        const int s  = __ldg(&g_offs[rrow]);
        const int en = __ldg(&g_offs[rrow + 1]);
        const bool flag = (s == en) || (s % Q == 0) || (en % Q == 0) ||
                          (en == nnz) || ((s / Q) != ((en - 1) / Q));
        if (flag)
            reinterpret_cast<float4*>(out + (size_t)rrow * D)[lane] =
                make_float4(0.f, 0.f, 0.f, 0.f);
    }
}

// ---------------------------------------------------------------------------
// K4: balanced gather (byte-identical to R13's proven 26.6us version).
// ---------------------------------------------------------------------------
__device__ __forceinline__ void acc_edge_cvt(uint2 hv, float c, float4& a) {
    const float2 f01 = __half22float2(*reinterpret_cast<const __half2*>(&hv.x));
    const float2 f23 = __half22float2(*reinterpret_cast<const __half2*>(&hv.y));
    a.x = fmaf(c, f01.x, a.x);
    a.y = fmaf(c, f01.y, a.y);
    a.z = fmaf(c, f23.x, a.z);
    a.w = fmaf(c, f23.y, a.w);
}

__device__ __forceinline__ void flush_row(float* __restrict__ out, int row,
                                          const float4& a, bool atomic, int lane) {
    float* p = out + (size_t)row * D + lane * 4;
    if (atomic) {
        asm volatile("red.global.add.v4.f32 [%0], {%1, %2, %3, %4};"
                     :: "l"(p), "f"(a.x), "f"(a.y), "f"(a.z), "f"(a.w)
                     : "memory");
    } else {
        *reinterpret_cast<float4*>(p) = a;
    }
}

__global__ void __launch_bounds__(128)
k_gather(float* __restrict__ out, int nnz) {
    const int lane = threadIdx.x & 31;
    const int wid  = (blockIdx.x * blockDim.x + threadIdx.x) >> 5;
    const int base = wid * Q;
    if (base >= nnz) return;
    const int end = min(base + Q, nnz);

    int   currow = (int)((unsigned)__ldg(&g_edges[base]) & 0xFFFFu);
    bool  first  = true;
    float4 acc   = make_float4(0.f, 0.f, 0.f, 0.f);

    int i = base;
    for (; i + 3 < end; i += 4) {
        const ulonglong2 ea = __ldg(reinterpret_cast<const ulonglong2*>(g_edges + i));
        const ulonglong2 eb = __ldg(reinterpret_cast<const ulonglong2*>(g_edges + i + 2));
        const uint2 v0 = __ldg(reinterpret_cast<const uint2*>(
                g_inh + (size_t)((unsigned)(ea.x >> 16) & 0xFFFFu) * D) + lane);
        const uint2 v1 = __ldg(reinterpret_cast<const uint2*>(
                g_inh + (size_t)((unsigned)(ea.y >> 16) & 0xFFFFu) * D) + lane);
        const uint2 v2 = __ldg(reinterpret_cast<const uint2*>(
                g_inh + (size_t)((unsigned)(eb.x >> 16) & 0xFFFFu) * D) + lane);
        const uint2 v3 = __ldg(reinterpret_cast<const uint2*>(
                g_inh + (size_t)((unsigned)(eb.y >> 16) & 0xFFFFu) * D) + lane);

        const unsigned long long eds[4] = {ea.x, ea.y, eb.x, eb.y};
        const uint2 vs[4] = {v0, v1, v2, v3};
#pragma unroll
        for (int k = 0; k < 4; k++) {
            const int row = (int)((unsigned)eds[k] & 0xFFFFu);
            if (row != currow) {
                flush_row(out, currow, acc, first, lane);
                first = false;
                acc = make_float4(0.f, 0.f, 0.f, 0.f);
                currow = row;
            }
            const float c = __uint_as_float((unsigned)(eds[k] >> 32));
            acc_edge_cvt(vs[k], c, acc);
        }
    }
    for (; i < end; i++) {
        const unsigned long long ed = __ldg(&g_edges[i]);
        const int row = (int)((unsigned)ed & 0xFFFFu);
        if (row != currow) {
            flush_row(out, currow, acc, first, lane);
            first = false;
            acc = make_float4(0.f, 0.f, 0.f, 0.f);
            currow = row;
        }
        const uint2 v = __ldg(reinterpret_cast<const uint2*>(
                g_inh + (size_t)((unsigned)(ed >> 16) & 0xFFFFu) * D) + lane);
        const float c = __uint_as_float((unsigned)(ed >> 32));
        acc_edge_cvt(v, c, acc);
    }
    flush_row(out, currow, acc, true, lane);
}

// ---------------------------------------------------------------------------
// kernel_launch
// Inputs: 0 inlayer [N,D] f32 | 1 dual [R,D] f32 | 2 conv_w [D] f32
//         3 conv_b [1] f32    | 4 edge_idx [2,NNZ] i32 | 5 edge_rel [NNZ] i32
// Output: [N, D] f32
// ---------------------------------------------------------------------------
extern "C" void kernel_launch(void* const* d_in, const int* in_sizes, int n_in,
                              void* d_out, int out_size) {
    const float* inlayer = (const float*)d_in[0];
    const float* dual    = (const float*)d_in[1];
    const float* conv_w  = (const float*)d_in[2];
    const float* conv_b  = (const float*)d_in[3];
    const int*   eidx    = (const int*)d_in[4];
    const int*   erel    = (const int*)d_in[5];
    float*       out     = (float*)d_out;

    const int nnz = in_sizes[5];
    const int* rowp = eidx;
    const int* colp = eidx + nnz;

    k_fused<<<FUSE_NB, 256>>>(inlayer, dual, conv_w, conv_b, rowp, erel, nnz);
    k_scan<<<SCAN_NB, SCAN_BLK>>>(nnz);
    k_reorder<<<(nnz / 8 + 255) / 256, 256>>>(rowp, colp, erel, nnz, out);

    const int nwarps = (nnz + Q - 1) / Q;                 // 12500
    k_gather<<<(nwarps * 32 + 127) / 128, 128>>>(out, nnz);
}